// round 1
// baseline (speedup 1.0000x reference)
#include <cuda_runtime.h>

// Problem constants
#define B_  2
#define C_  1024
#define E_  1024
#define HD_ 64
#define H_  16

// Scratch (device globals — no allocation allowed)
__device__ float g_Q[B_ * C_ * E_];
__device__ float g_K[B_ * C_ * E_];
__device__ float g_V[B_ * C_ * E_];
__device__ float g_AO[B_ * C_ * E_];

// ---------------------------------------------------------------------------
// NT GEMM: Cd[m,n] = sum_k A[m,k] * W[n,k]
// M=2048, N=1024, K=1024 fixed. 64x64 block tile, BK=16, 256 threads, 4x4/thread.
// REMAP=1: write into attention layout [b*64+hd][c][h] (for Q/K/V projections).
// REMAP=0: write row-major [m,n] (for output projection).
// ---------------------------------------------------------------------------
template <int REMAP>
__global__ void __launch_bounds__(256, 4)
gemm_nt(const float* __restrict__ A, const float* __restrict__ W,
        float* __restrict__ Cd)
{
    const int K = 1024;
    __shared__ float As[16][68];
    __shared__ float Bs[16][68];

    const int t  = threadIdx.x;
    const int bm = blockIdx.y * 64;
    const int bn = blockIdx.x * 64;

    const int lr = t >> 2;          // 0..63 : tile row loaded by this thread
    const int lk = (t & 3) << 2;    // 0,4,8,12 : k-offset (float4)
    const int tx = t & 15;          // 0..15
    const int ty = t >> 4;          // 0..15

    float acc[4][4] = {};

    const float* Ap = A + (size_t)(bm + lr) * K + lk;
    const float* Wp = W + (size_t)(bn + lr) * K + lk;

    for (int k0 = 0; k0 < K; k0 += 16) {
        float4 a = *(const float4*)(Ap + k0);
        float4 b = *(const float4*)(Wp + k0);
        As[lk + 0][lr] = a.x; As[lk + 1][lr] = a.y;
        As[lk + 2][lr] = a.z; As[lk + 3][lr] = a.w;
        Bs[lk + 0][lr] = b.x; Bs[lk + 1][lr] = b.y;
        Bs[lk + 2][lr] = b.z; Bs[lk + 3][lr] = b.w;
        __syncthreads();

        #pragma unroll
        for (int k = 0; k < 16; k++) {
            float4 av4 = *(const float4*)&As[k][ty << 2];
            float4 bv4 = *(const float4*)&Bs[k][tx << 2];
            float av[4] = {av4.x, av4.y, av4.z, av4.w};
            float bv[4] = {bv4.x, bv4.y, bv4.z, bv4.w};
            #pragma unroll
            for (int i = 0; i < 4; i++)
                #pragma unroll
                for (int j = 0; j < 4; j++)
                    acc[i][j] += av[i] * bv[j];
        }
        __syncthreads();
    }

    #pragma unroll
    for (int i = 0; i < 4; i++) {
        const int m = bm + (ty << 2) + i;
        const int b = m >> 10;          // batch
        const int c = m & 1023;         // seq pos
        #pragma unroll
        for (int j = 0; j < 4; j++) {
            const int n = bn + (tx << 2) + j;
            if (REMAP) {
                const int hd = n >> 4;
                const int h  = n & 15;
                // [bh][c][h] with bh = b*64+hd, row stride 16
                Cd[(((size_t)(b * 64 + hd)) << 14) + (size_t)c * 16 + h] = acc[i][j];
            } else {
                Cd[(size_t)m * 1024 + n] = acc[i][j];
            }
        }
    }
}

// ---------------------------------------------------------------------------
// Flash-style attention. One thread = one query row.
// grid = (C/128, B*HD), block = 128 threads.
// Q/K/V layout: [bh][c][h], 16 floats per row (contiguous).
// Output written into [B,C,E] layout (e = hd*16 + h) for the O projection.
// ---------------------------------------------------------------------------
__global__ void __launch_bounds__(128)
attn_kernel(float* __restrict__ O)
{
    __shared__ float Ks[128][16];
    __shared__ float Vs[128][16];

    const int bh = blockIdx.y;                     // 0..127
    const int t  = threadIdx.x;
    const int c  = blockIdx.x * 128 + t;           // query row 0..1023

    const float* qp = g_Q + ((size_t)bh * 1024 + c) * 16;
    float q[16];
    #pragma unroll
    for (int i = 0; i < 4; i++) {
        float4 v = *(const float4*)(qp + i * 4);
        q[i * 4 + 0] = v.x; q[i * 4 + 1] = v.y;
        q[i * 4 + 2] = v.z; q[i * 4 + 3] = v.w;
    }

    float m = -1e30f, l = 0.0f;
    float o[16] = {};

    const float* kbase = g_K + (size_t)bh * 1024 * 16;
    const float* vbase = g_V + (size_t)bh * 1024 * 16;

    for (int kt = 0; kt < 1024; kt += 128) {
        // cooperative tile load: thread t loads K/V row (kt+t)
        const float4* kp = (const float4*)(kbase + (size_t)(kt + t) * 16);
        const float4* vp = (const float4*)(vbase + (size_t)(kt + t) * 16);
        #pragma unroll
        for (int i = 0; i < 4; i++) {
            ((float4*)Ks[t])[i] = kp[i];
            ((float4*)Vs[t])[i] = vp[i];
        }
        __syncthreads();

        #pragma unroll 1
        for (int c0 = 0; c0 < 128; c0 += 16) {
            float s[16];
            #pragma unroll
            for (int jj = 0; jj < 16; jj++) {
                const float4* kr = (const float4*)Ks[c0 + jj];
                float4 k0 = kr[0], k1 = kr[1], k2 = kr[2], k3 = kr[3];
                float a0;
                a0  = q[0]  * k0.x; a0 += q[1]  * k0.y;
                a0 += q[2]  * k0.z; a0 += q[3]  * k0.w;
                a0 += q[4]  * k1.x; a0 += q[5]  * k1.y;
                a0 += q[6]  * k1.z; a0 += q[7]  * k1.w;
                a0 += q[8]  * k2.x; a0 += q[9]  * k2.y;
                a0 += q[10] * k2.z; a0 += q[11] * k2.w;
                a0 += q[12] * k3.x; a0 += q[13] * k3.y;
                a0 += q[14] * k3.z; a0 += q[15] * k3.w;
                s[jj] = a0 * 0.25f;   // scale = 1/sqrt(H=16)
            }
            float cm = s[0];
            #pragma unroll
            for (int jj = 1; jj < 16; jj++) cm = fmaxf(cm, s[jj]);
            const float mnew = fmaxf(m, cm);
            const float corr = __expf(m - mnew);
            l *= corr;
            #pragma unroll
            for (int h = 0; h < 16; h++) o[h] *= corr;

            #pragma unroll
            for (int jj = 0; jj < 16; jj++) {
                const float p = __expf(s[jj] - mnew);
                l += p;
                const float4* vr = (const float4*)Vs[c0 + jj];
                float4 v0 = vr[0], v1 = vr[1], v2 = vr[2], v3 = vr[3];
                o[0]  += p * v0.x; o[1]  += p * v0.y;
                o[2]  += p * v0.z; o[3]  += p * v0.w;
                o[4]  += p * v1.x; o[5]  += p * v1.y;
                o[6]  += p * v1.z; o[7]  += p * v1.w;
                o[8]  += p * v2.x; o[9]  += p * v2.y;
                o[10] += p * v2.z; o[11] += p * v2.w;
                o[12] += p * v3.x; o[13] += p * v3.y;
                o[14] += p * v3.z; o[15] += p * v3.w;
            }
            m = mnew;
        }
        __syncthreads();
    }

    const float inv = 1.0f / l;
    const int b  = bh >> 6;
    const int hd = bh & 63;
    float* op = O + ((size_t)(b * 1024 + c)) * 1024 + hd * 16;
    #pragma unroll
    for (int i = 0; i < 4; i++) {
        float4 v = make_float4(o[i * 4 + 0] * inv, o[i * 4 + 1] * inv,
                               o[i * 4 + 2] * inv, o[i * 4 + 3] * inv);
        *(float4*)(op + i * 4) = v;
    }
}

// ---------------------------------------------------------------------------
// Launch
// ---------------------------------------------------------------------------
extern "C" void kernel_launch(void* const* d_in, const int* in_sizes, int n_in,
                              void* d_out, int out_size)
{
    const float* x  = (const float*)d_in[0];
    const float* Wq = (const float*)d_in[1];
    const float* Wk = (const float*)d_in[2];
    const float* Wv = (const float*)d_in[3];
    const float* Wo = (const float*)d_in[4];
    float* out = (float*)d_out;

    float *pQ, *pK, *pV, *pAO;
    cudaGetSymbolAddress((void**)&pQ,  g_Q);
    cudaGetSymbolAddress((void**)&pK,  g_K);
    cudaGetSymbolAddress((void**)&pV,  g_V);
    cudaGetSymbolAddress((void**)&pAO, g_AO);

    dim3 gg(1024 / 64, 2048 / 64);   // (N tiles, M tiles)
    gemm_nt<1><<<gg, 256>>>(x, Wq, pQ);
    gemm_nt<1><<<gg, 256>>>(x, Wk, pK);
    gemm_nt<1><<<gg, 256>>>(x, Wv, pV);

    attn_kernel<<<dim3(1024 / 128, B_ * HD_), 128>>>(pAO);

    gemm_nt<0><<<gg, 256>>>(pAO, Wo, out);
}

// round 2
// speedup vs baseline: 1.3516x; 1.3516x over previous
#include <cuda_runtime.h>

#define B_  2
#define C_  1024
#define E_  1024
#define HD_ 64
#define H_  16

// Scratch (device globals — no allocation allowed)
__device__ float g_Q[B_ * C_ * E_];
__device__ float g_K[B_ * C_ * E_];
__device__ float g_V[B_ * C_ * E_];
__device__ float g_AO[B_ * C_ * E_];

typedef unsigned long long u64;

__device__ __forceinline__ u64 fma2(u64 a, u64 b, u64 c) {
    u64 d;
    asm("fma.rn.f32x2 %0, %1, %2, %3;" : "=l"(d) : "l"(a), "l"(b), "l"(c));
    return d;
}
__device__ __forceinline__ u64 mul2(u64 a, u64 b) {
    u64 d;
    asm("mul.rn.f32x2 %0, %1, %2;" : "=l"(d) : "l"(a), "l"(b));
    return d;
}
__device__ __forceinline__ u64 pack2(float lo, float hi) {
    u64 d;
    asm("mov.b64 %0, {%1, %2};" : "=l"(d) : "f"(lo), "f"(hi));
    return d;
}
__device__ __forceinline__ u64 splat2(float x) {
    u64 d;
    asm("mov.b64 %0, {%1, %1};" : "=l"(d) : "f"(x));
    return d;
}
__device__ __forceinline__ void unpack2(u64 v, float& lo, float& hi) {
    asm("mov.b64 {%0, %1}, %2;" : "=f"(lo), "=f"(hi) : "l"(v));
}

// ---------------------------------------------------------------------------
// NT GEMM with packed f32x2 FMA. Cd[m,n] = sum_k A[m,k] * W[n,k]
// M=2048, N=1024, K=1024. 128x128 tile, BK=16, 256 threads, 8x8 microtile
// (split 4+4 in both dims for conflict-free smem loads).
// REMAP=1: write into attention layout [b*64+hd][c][h].
// REMAP=0: row-major [m,n].
// ---------------------------------------------------------------------------
template <int REMAP>
__global__ void __launch_bounds__(256, 2)
gemm_nt2(const float* __restrict__ A, const float* __restrict__ W,
         float* __restrict__ Cd)
{
    const int K = 1024;
    __shared__ __align__(16) float As[16][132];
    __shared__ __align__(16) float Bs[16][132];

    const int t  = threadIdx.x;
    const int bm = blockIdx.y * 128;
    const int bn = blockIdx.x * 128;

    // global-load mapping: each thread loads 8 consecutive k-floats of one row
    const int lr = t >> 1;            // 0..127
    const int lk = (t & 1) << 3;      // 0 or 8

    // compute mapping: 8 warps as 4(m) x 2(n); lane as 4(m) x 8(n)
    const int warp = t >> 5, lane = t & 31;
    const int wm = (warp >> 1) * 32;  // warp m-offset (covers 32 rows)
    const int wn = (warp & 1) * 64;   // warp n-offset (covers 64 cols)
    const int lm = (lane >> 3) * 4;   // 0,4,8,12
    const int ln = (lane & 7) * 4;    // 0..28

    // acc[ih][i][jh][jp] : u64 covers output cols (n, n+1)
    u64 acc[2][4][2][2];
    #pragma unroll
    for (int a = 0; a < 2; a++)
        #pragma unroll
        for (int b = 0; b < 4; b++)
            #pragma unroll
            for (int c = 0; c < 2; c++) { acc[a][b][c][0] = 0ull; acc[a][b][c][1] = 0ull; }

    const float* Ap = A + (size_t)(bm + lr) * K + lk;
    const float* Wp = W + (size_t)(bn + lr) * K + lk;

    float4 pa0 = *(const float4*)(Ap);
    float4 pa1 = *(const float4*)(Ap + 4);
    float4 pb0 = *(const float4*)(Wp);
    float4 pb1 = *(const float4*)(Wp + 4);

    for (int k0 = 0; k0 < K; k0 += 16) {
        // stage current tile (transposed: As[k][row])
        As[lk + 0][lr] = pa0.x; As[lk + 1][lr] = pa0.y;
        As[lk + 2][lr] = pa0.z; As[lk + 3][lr] = pa0.w;
        As[lk + 4][lr] = pa1.x; As[lk + 5][lr] = pa1.y;
        As[lk + 6][lr] = pa1.z; As[lk + 7][lr] = pa1.w;
        Bs[lk + 0][lr] = pb0.x; Bs[lk + 1][lr] = pb0.y;
        Bs[lk + 2][lr] = pb0.z; Bs[lk + 3][lr] = pb0.w;
        Bs[lk + 4][lr] = pb1.x; Bs[lk + 5][lr] = pb1.y;
        Bs[lk + 6][lr] = pb1.z; Bs[lk + 7][lr] = pb1.w;
        __syncthreads();

        if (k0 + 16 < K) {  // prefetch next tile under the compute
            pa0 = *(const float4*)(Ap + k0 + 16);
            pa1 = *(const float4*)(Ap + k0 + 20);
            pb0 = *(const float4*)(Wp + k0 + 16);
            pb1 = *(const float4*)(Wp + k0 + 20);
        }

        #pragma unroll
        for (int k = 0; k < 16; k++) {
            float4 a0 = *(const float4*)&As[k][wm + lm];
            float4 a1 = *(const float4*)&As[k][wm + lm + 16];
            const u64* b0 = (const u64*)&Bs[k][wn + ln];        // 2 u64 (4 floats)
            const u64* b1 = (const u64*)&Bs[k][wn + ln + 32];   // 2 u64
            u64 bb[2][2] = {{b0[0], b0[1]}, {b1[0], b1[1]}};
            u64 av[2][4];
            av[0][0] = splat2(a0.x); av[0][1] = splat2(a0.y);
            av[0][2] = splat2(a0.z); av[0][3] = splat2(a0.w);
            av[1][0] = splat2(a1.x); av[1][1] = splat2(a1.y);
            av[1][2] = splat2(a1.z); av[1][3] = splat2(a1.w);
            #pragma unroll
            for (int ih = 0; ih < 2; ih++)
                #pragma unroll
                for (int i = 0; i < 4; i++)
                    #pragma unroll
                    for (int jh = 0; jh < 2; jh++) {
                        acc[ih][i][jh][0] = fma2(av[ih][i], bb[jh][0], acc[ih][i][jh][0]);
                        acc[ih][i][jh][1] = fma2(av[ih][i], bb[jh][1], acc[ih][i][jh][1]);
                    }
        }
        __syncthreads();
    }

    // epilogue: 16 float4 stores per thread
    #pragma unroll
    for (int ih = 0; ih < 2; ih++) {
        #pragma unroll
        for (int i = 0; i < 4; i++) {
            const int m = bm + wm + ih * 16 + lm + i;
            const int b = m >> 10;
            const int c = m & 1023;
            #pragma unroll
            for (int jh = 0; jh < 2; jh++) {
                const int n = bn + wn + jh * 32 + ln;   // n % 4 == 0
                float4 v;
                unpack2(acc[ih][i][jh][0], v.x, v.y);
                unpack2(acc[ih][i][jh][1], v.z, v.w);
                if (REMAP) {
                    const int hd = n >> 4;
                    const int h  = n & 15;  // h % 4 == 0 -> contiguous quad
                    *(float4*)&Cd[(((size_t)(b * 64 + hd)) << 14) + (size_t)c * 16 + h] = v;
                } else {
                    *(float4*)&Cd[(size_t)m * 1024 + n] = v;
                }
            }
        }
    }
}

// ---------------------------------------------------------------------------
// Flash-style attention with packed f32x2 math. One thread = one query row.
// grid = (C/128, B*HD), block = 128. Q/K/V layout: [bh][c][16].
// ---------------------------------------------------------------------------
__global__ void __launch_bounds__(128)
attn_kernel2(float* __restrict__ O)
{
    __shared__ __align__(16) float Ks[128][16];
    __shared__ __align__(16) float Vs[128][16];

    const int bh = blockIdx.y;
    const int t  = threadIdx.x;
    const int c  = blockIdx.x * 128 + t;

    // load q, fold in scale 0.25 (exact), pack into 8 f32x2
    const float* qp = g_Q + ((size_t)bh * 1024 + c) * 16;
    u64 q2[8];
    #pragma unroll
    for (int i = 0; i < 4; i++) {
        float4 v = *(const float4*)(qp + i * 4);
        q2[i * 2 + 0] = pack2(v.x * 0.25f, v.y * 0.25f);
        q2[i * 2 + 1] = pack2(v.z * 0.25f, v.w * 0.25f);
    }

    float m = -1e30f, l = 0.0f;
    u64 o2[8];
    #pragma unroll
    for (int i = 0; i < 8; i++) o2[i] = 0ull;

    const float* kbase = g_K + (size_t)bh * 1024 * 16;
    const float* vbase = g_V + (size_t)bh * 1024 * 16;

    for (int kt = 0; kt < 1024; kt += 128) {
        const float4* kp = (const float4*)(kbase + (size_t)(kt + t) * 16);
        const float4* vp = (const float4*)(vbase + (size_t)(kt + t) * 16);
        #pragma unroll
        for (int i = 0; i < 4; i++) {
            ((float4*)Ks[t])[i] = kp[i];
            ((float4*)Vs[t])[i] = vp[i];
        }
        __syncthreads();

        #pragma unroll 1
        for (int c0 = 0; c0 < 128; c0 += 16) {
            float s[16];
            #pragma unroll
            for (int jj = 0; jj < 16; jj++) {
                const u64* kr = (const u64*)Ks[c0 + jj];
                u64 acc = mul2(q2[0], kr[0]);
                acc = fma2(q2[1], kr[1], acc);
                acc = fma2(q2[2], kr[2], acc);
                acc = fma2(q2[3], kr[3], acc);
                acc = fma2(q2[4], kr[4], acc);
                acc = fma2(q2[5], kr[5], acc);
                acc = fma2(q2[6], kr[6], acc);
                acc = fma2(q2[7], kr[7], acc);
                float lo, hi; unpack2(acc, lo, hi);
                s[jj] = lo + hi;
            }
            float cm = s[0];
            #pragma unroll
            for (int jj = 1; jj < 16; jj++) cm = fmaxf(cm, s[jj]);
            const float mnew = fmaxf(m, cm);
            const float corr = __expf(m - mnew);
            l *= corr;
            const u64 corr2 = splat2(corr);
            #pragma unroll
            for (int h = 0; h < 8; h++) o2[h] = mul2(o2[h], corr2);

            #pragma unroll
            for (int jj = 0; jj < 16; jj++) {
                const float p = __expf(s[jj] - mnew);
                l += p;
                const u64 pp = splat2(p);
                const u64* vr = (const u64*)Vs[c0 + jj];
                o2[0] = fma2(pp, vr[0], o2[0]);
                o2[1] = fma2(pp, vr[1], o2[1]);
                o2[2] = fma2(pp, vr[2], o2[2]);
                o2[3] = fma2(pp, vr[3], o2[3]);
                o2[4] = fma2(pp, vr[4], o2[4]);
                o2[5] = fma2(pp, vr[5], o2[5]);
                o2[6] = fma2(pp, vr[6], o2[6]);
                o2[7] = fma2(pp, vr[7], o2[7]);
            }
            m = mnew;
        }
        __syncthreads();
    }

    const float inv = 1.0f / l;
    const int b  = bh >> 6;
    const int hd = bh & 63;
    float* op = O + ((size_t)(b * 1024 + c)) * 1024 + hd * 16;
    #pragma unroll
    for (int i = 0; i < 4; i++) {
        float lo0, hi0, lo1, hi1;
        unpack2(o2[i * 2 + 0], lo0, hi0);
        unpack2(o2[i * 2 + 1], lo1, hi1);
        *(float4*)(op + i * 4) =
            make_float4(lo0 * inv, hi0 * inv, lo1 * inv, hi1 * inv);
    }
}

// ---------------------------------------------------------------------------
extern "C" void kernel_launch(void* const* d_in, const int* in_sizes, int n_in,
                              void* d_out, int out_size)
{
    const float* x  = (const float*)d_in[0];
    const float* Wq = (const float*)d_in[1];
    const float* Wk = (const float*)d_in[2];
    const float* Wv = (const float*)d_in[3];
    const float* Wo = (const float*)d_in[4];
    float* out = (float*)d_out;

    float *pQ, *pK, *pV, *pAO;
    cudaGetSymbolAddress((void**)&pQ,  g_Q);
    cudaGetSymbolAddress((void**)&pK,  g_K);
    cudaGetSymbolAddress((void**)&pV,  g_V);
    cudaGetSymbolAddress((void**)&pAO, g_AO);

    dim3 gg(1024 / 128, 2048 / 128);  // (N tiles, M tiles) = (8, 16) = 128 blocks
    gemm_nt2<1><<<gg, 256>>>(x, Wq, pQ);
    gemm_nt2<1><<<gg, 256>>>(x, Wk, pK);
    gemm_nt2<1><<<gg, 256>>>(x, Wv, pV);

    attn_kernel2<<<dim3(1024 / 128, B_ * HD_), 128>>>(pAO);

    gemm_nt2<0><<<gg, 256>>>(pAO, Wo, out);
}

// round 3
// speedup vs baseline: 1.4096x; 1.0429x over previous
#include <cuda_runtime.h>

#define B_  2
#define C_  1024
#define E_  1024
#define HD_ 64
#define H_  16

// Scratch (device globals — no allocation allowed)
__device__ float g_Q[B_ * C_ * E_];
__device__ float g_K[B_ * C_ * E_];
__device__ float g_V[B_ * C_ * E_];
__device__ float g_AO[B_ * C_ * E_];

typedef unsigned long long u64;

__device__ __forceinline__ u64 fma2(u64 a, u64 b, u64 c) {
    u64 d;
    asm("fma.rn.f32x2 %0, %1, %2, %3;" : "=l"(d) : "l"(a), "l"(b), "l"(c));
    return d;
}
__device__ __forceinline__ u64 mul2(u64 a, u64 b) {
    u64 d;
    asm("mul.rn.f32x2 %0, %1, %2;" : "=l"(d) : "l"(a), "l"(b));
    return d;
}
__device__ __forceinline__ u64 pack2(float lo, float hi) {
    u64 d;
    asm("mov.b64 %0, {%1, %2};" : "=l"(d) : "f"(lo), "f"(hi));
    return d;
}
__device__ __forceinline__ u64 splat2(float x) {
    u64 d;
    asm("mov.b64 %0, {%1, %1};" : "=l"(d) : "f"(x));
    return d;
}
__device__ __forceinline__ void unpack2(u64 v, float& lo, float& hi) {
    asm("mov.b64 {%0, %1}, %2;" : "=f"(lo), "=f"(hi) : "l"(v));
}

// ---------------------------------------------------------------------------
// NT GEMM with packed f32x2 FMA (unchanged from R2 — ~67% of FFMA2 roofline).
// ---------------------------------------------------------------------------
template <int REMAP>
__global__ void __launch_bounds__(256, 2)
gemm_nt2(const float* __restrict__ A, const float* __restrict__ W,
         float* __restrict__ Cd)
{
    const int K = 1024;
    __shared__ __align__(16) float As[16][132];
    __shared__ __align__(16) float Bs[16][132];

    const int t  = threadIdx.x;
    const int bm = blockIdx.y * 128;
    const int bn = blockIdx.x * 128;

    const int lr = t >> 1;
    const int lk = (t & 1) << 3;

    const int warp = t >> 5, lane = t & 31;
    const int wm = (warp >> 1) * 32;
    const int wn = (warp & 1) * 64;
    const int lm = (lane >> 3) * 4;
    const int ln = (lane & 7) * 4;

    u64 acc[2][4][2][2];
    #pragma unroll
    for (int a = 0; a < 2; a++)
        #pragma unroll
        for (int b = 0; b < 4; b++)
            #pragma unroll
            for (int c = 0; c < 2; c++) { acc[a][b][c][0] = 0ull; acc[a][b][c][1] = 0ull; }

    const float* Ap = A + (size_t)(bm + lr) * K + lk;
    const float* Wp = W + (size_t)(bn + lr) * K + lk;

    float4 pa0 = *(const float4*)(Ap);
    float4 pa1 = *(const float4*)(Ap + 4);
    float4 pb0 = *(const float4*)(Wp);
    float4 pb1 = *(const float4*)(Wp + 4);

    for (int k0 = 0; k0 < K; k0 += 16) {
        As[lk + 0][lr] = pa0.x; As[lk + 1][lr] = pa0.y;
        As[lk + 2][lr] = pa0.z; As[lk + 3][lr] = pa0.w;
        As[lk + 4][lr] = pa1.x; As[lk + 5][lr] = pa1.y;
        As[lk + 6][lr] = pa1.z; As[lk + 7][lr] = pa1.w;
        Bs[lk + 0][lr] = pb0.x; Bs[lk + 1][lr] = pb0.y;
        Bs[lk + 2][lr] = pb0.z; Bs[lk + 3][lr] = pb0.w;
        Bs[lk + 4][lr] = pb1.x; Bs[lk + 5][lr] = pb1.y;
        Bs[lk + 6][lr] = pb1.z; Bs[lk + 7][lr] = pb1.w;
        __syncthreads();

        if (k0 + 16 < K) {
            pa0 = *(const float4*)(Ap + k0 + 16);
            pa1 = *(const float4*)(Ap + k0 + 20);
            pb0 = *(const float4*)(Wp + k0 + 16);
            pb1 = *(const float4*)(Wp + k0 + 20);
        }

        #pragma unroll
        for (int k = 0; k < 16; k++) {
            float4 a0 = *(const float4*)&As[k][wm + lm];
            float4 a1 = *(const float4*)&As[k][wm + lm + 16];
            const u64* b0 = (const u64*)&Bs[k][wn + ln];
            const u64* b1 = (const u64*)&Bs[k][wn + ln + 32];
            u64 bb[2][2] = {{b0[0], b0[1]}, {b1[0], b1[1]}};
            u64 av[2][4];
            av[0][0] = splat2(a0.x); av[0][1] = splat2(a0.y);
            av[0][2] = splat2(a0.z); av[0][3] = splat2(a0.w);
            av[1][0] = splat2(a1.x); av[1][1] = splat2(a1.y);
            av[1][2] = splat2(a1.z); av[1][3] = splat2(a1.w);
            #pragma unroll
            for (int ih = 0; ih < 2; ih++)
                #pragma unroll
                for (int i = 0; i < 4; i++)
                    #pragma unroll
                    for (int jh = 0; jh < 2; jh++) {
                        acc[ih][i][jh][0] = fma2(av[ih][i], bb[jh][0], acc[ih][i][jh][0]);
                        acc[ih][i][jh][1] = fma2(av[ih][i], bb[jh][1], acc[ih][i][jh][1]);
                    }
        }
        __syncthreads();
    }

    #pragma unroll
    for (int ih = 0; ih < 2; ih++) {
        #pragma unroll
        for (int i = 0; i < 4; i++) {
            const int m = bm + wm + ih * 16 + lm + i;
            const int b = m >> 10;
            const int c = m & 1023;
            #pragma unroll
            for (int jh = 0; jh < 2; jh++) {
                const int n = bn + wn + jh * 32 + ln;
                float4 v;
                unpack2(acc[ih][i][jh][0], v.x, v.y);
                unpack2(acc[ih][i][jh][1], v.z, v.w);
                if (REMAP) {
                    const int hd = n >> 4;
                    const int h  = n & 15;
                    *(float4*)&Cd[(((size_t)(b * 64 + hd)) << 14) + (size_t)c * 16 + h] = v;
                } else {
                    *(float4*)&Cd[(size_t)m * 1024 + n] = v;
                }
            }
        }
    }
}

// ---------------------------------------------------------------------------
// Flash attention v3: 2 query rows per thread, LDS.128 K/V reads.
// grid = (C/256, B*HD), block = 128. Thread t handles queries
// (blk*256 + t) and (blk*256 + 128 + t). K/V layout: [bh][c][16].
// ---------------------------------------------------------------------------
__global__ void __launch_bounds__(128)
attn_kernel3(float* __restrict__ O)
{
    __shared__ __align__(16) float Ks[128][16];
    __shared__ __align__(16) float Vs[128][16];

    const int bh = blockIdx.y;
    const int t  = threadIdx.x;
    const int cq0 = blockIdx.x * 256 + t;        // query row A
    const int cq1 = cq0 + 128;                   // query row B

    // load both q rows, fold scale 0.25 (exact), pack into f32x2
    u64 q2[2][8];
    #pragma unroll
    for (int qq = 0; qq < 2; qq++) {
        const float* qp = g_Q + ((size_t)bh * 1024 + (qq ? cq1 : cq0)) * 16;
        #pragma unroll
        for (int i = 0; i < 4; i++) {
            float4 v = *(const float4*)(qp + i * 4);
            q2[qq][i * 2 + 0] = pack2(v.x * 0.25f, v.y * 0.25f);
            q2[qq][i * 2 + 1] = pack2(v.z * 0.25f, v.w * 0.25f);
        }
    }

    float m0 = -1e30f, l0 = 0.0f, m1 = -1e30f, l1 = 0.0f;
    u64 o2[2][8];
    #pragma unroll
    for (int i = 0; i < 8; i++) { o2[0][i] = 0ull; o2[1][i] = 0ull; }

    const float* kbase = g_K + (size_t)bh * 1024 * 16;
    const float* vbase = g_V + (size_t)bh * 1024 * 16;

    for (int kt = 0; kt < 1024; kt += 128) {
        const float4* kp = (const float4*)(kbase + (size_t)(kt + t) * 16);
        const float4* vp = (const float4*)(vbase + (size_t)(kt + t) * 16);
        #pragma unroll
        for (int i = 0; i < 4; i++) {
            ((float4*)Ks[t])[i] = kp[i];
            ((float4*)Vs[t])[i] = vp[i];
        }
        __syncthreads();

        #pragma unroll 1
        for (int c0 = 0; c0 < 128; c0 += 16) {
            float s0[16], s1[16];
            #pragma unroll
            for (int jj = 0; jj < 16; jj++) {
                // K row: 4 x LDS.128 (broadcast), gives 8 u64
                const ulonglong2* krp = (const ulonglong2*)Ks[c0 + jj];
                ulonglong2 ka = krp[0], kb = krp[1], kc = krp[2], kd = krp[3];
                u64 a0 = mul2(q2[0][0], ka.x);
                u64 a1 = mul2(q2[1][0], ka.x);
                a0 = fma2(q2[0][1], ka.y, a0); a1 = fma2(q2[1][1], ka.y, a1);
                a0 = fma2(q2[0][2], kb.x, a0); a1 = fma2(q2[1][2], kb.x, a1);
                a0 = fma2(q2[0][3], kb.y, a0); a1 = fma2(q2[1][3], kb.y, a1);
                a0 = fma2(q2[0][4], kc.x, a0); a1 = fma2(q2[1][4], kc.x, a1);
                a0 = fma2(q2[0][5], kc.y, a0); a1 = fma2(q2[1][5], kc.y, a1);
                a0 = fma2(q2[0][6], kd.x, a0); a1 = fma2(q2[1][6], kd.x, a1);
                a0 = fma2(q2[0][7], kd.y, a0); a1 = fma2(q2[1][7], kd.y, a1);
                float lo, hi;
                unpack2(a0, lo, hi); s0[jj] = lo + hi;
                unpack2(a1, lo, hi); s1[jj] = lo + hi;
            }
            float cm0 = s0[0], cm1 = s1[0];
            #pragma unroll
            for (int jj = 1; jj < 16; jj++) {
                cm0 = fmaxf(cm0, s0[jj]);
                cm1 = fmaxf(cm1, s1[jj]);
            }
            const float mn0 = fmaxf(m0, cm0);
            const float mn1 = fmaxf(m1, cm1);
            const float cr0 = __expf(m0 - mn0);
            const float cr1 = __expf(m1 - mn1);
            l0 *= cr0; l1 *= cr1;
            const u64 cr02 = splat2(cr0), cr12 = splat2(cr1);
            #pragma unroll
            for (int h = 0; h < 8; h++) {
                o2[0][h] = mul2(o2[0][h], cr02);
                o2[1][h] = mul2(o2[1][h], cr12);
            }

            #pragma unroll
            for (int jj = 0; jj < 16; jj++) {
                const float p0 = __expf(s0[jj] - mn0);
                const float p1 = __expf(s1[jj] - mn1);
                l0 += p0; l1 += p1;
                const u64 pp0 = splat2(p0), pp1 = splat2(p1);
                const ulonglong2* vrp = (const ulonglong2*)Vs[c0 + jj];
                ulonglong2 va = vrp[0], vb = vrp[1], vc = vrp[2], vd = vrp[3];
                o2[0][0] = fma2(pp0, va.x, o2[0][0]); o2[1][0] = fma2(pp1, va.x, o2[1][0]);
                o2[0][1] = fma2(pp0, va.y, o2[0][1]); o2[1][1] = fma2(pp1, va.y, o2[1][1]);
                o2[0][2] = fma2(pp0, vb.x, o2[0][2]); o2[1][2] = fma2(pp1, vb.x, o2[1][2]);
                o2[0][3] = fma2(pp0, vb.y, o2[0][3]); o2[1][3] = fma2(pp1, vb.y, o2[1][3]);
                o2[0][4] = fma2(pp0, vc.x, o2[0][4]); o2[1][4] = fma2(pp1, vc.x, o2[1][4]);
                o2[0][5] = fma2(pp0, vc.y, o2[0][5]); o2[1][5] = fma2(pp1, vc.y, o2[1][5]);
                o2[0][6] = fma2(pp0, vd.x, o2[0][6]); o2[1][6] = fma2(pp1, vd.x, o2[1][6]);
                o2[0][7] = fma2(pp0, vd.y, o2[0][7]); o2[1][7] = fma2(pp1, vd.y, o2[1][7]);
            }
            m0 = mn0; m1 = mn1;
        }
        __syncthreads();
    }

    const int b  = bh >> 6;
    const int hd = bh & 63;
    #pragma unroll
    for (int qq = 0; qq < 2; qq++) {
        const float inv = 1.0f / (qq ? l1 : l0);
        const int c = qq ? cq1 : cq0;
        float* op = O + ((size_t)(b * 1024 + c)) * 1024 + hd * 16;
        #pragma unroll
        for (int i = 0; i < 4; i++) {
            float x0, y0, x1, y1;
            unpack2(o2[qq][i * 2 + 0], x0, y0);
            unpack2(o2[qq][i * 2 + 1], x1, y1);
            *(float4*)(op + i * 4) =
                make_float4(x0 * inv, y0 * inv, x1 * inv, y1 * inv);
        }
    }
}

// ---------------------------------------------------------------------------
extern "C" void kernel_launch(void* const* d_in, const int* in_sizes, int n_in,
                              void* d_out, int out_size)
{
    const float* x  = (const float*)d_in[0];
    const float* Wq = (const float*)d_in[1];
    const float* Wk = (const float*)d_in[2];
    const float* Wv = (const float*)d_in[3];
    const float* Wo = (const float*)d_in[4];
    float* out = (float*)d_out;

    float *pQ, *pK, *pV, *pAO;
    cudaGetSymbolAddress((void**)&pQ,  g_Q);
    cudaGetSymbolAddress((void**)&pK,  g_K);
    cudaGetSymbolAddress((void**)&pV,  g_V);
    cudaGetSymbolAddress((void**)&pAO, g_AO);

    dim3 gg(1024 / 128, 2048 / 128);
    gemm_nt2<1><<<gg, 256>>>(x, Wq, pQ);
    gemm_nt2<1><<<gg, 256>>>(x, Wk, pK);
    gemm_nt2<1><<<gg, 256>>>(x, Wv, pV);

    attn_kernel3<<<dim3(1024 / 256, B_ * HD_), 128>>>(pAO);

    gemm_nt2<0><<<gg, 256>>>(pAO, Wo, out);
}

// round 5
// speedup vs baseline: 1.9482x; 1.3821x over previous
#include <cuda_runtime.h>
#include <cuda_bf16.h>
#include <cstdint>

#define B_  2
#define C_  1024
#define E_  1024
#define HD_ 64
#define H_  16

// Scratch (device globals — no allocation allowed)
__device__ float g_Q[B_ * C_ * E_];
__device__ float g_K[B_ * C_ * E_];
__device__ float g_V[B_ * C_ * E_];
__device__ __nv_bfloat16 g_xh[B_ * C_ * E_];
__device__ __nv_bfloat16 g_xl[B_ * C_ * E_];
__device__ __nv_bfloat16 g_Wh[4 * E_ * E_];
__device__ __nv_bfloat16 g_Wl[4 * E_ * E_];
__device__ __nv_bfloat16 g_AOh[B_ * C_ * E_];
__device__ __nv_bfloat16 g_AOl[B_ * C_ * E_];

typedef unsigned long long u64;

// ---------------- f32x2 helpers (attention) ----------------
__device__ __forceinline__ u64 fma2(u64 a, u64 b, u64 c) {
    u64 d; asm("fma.rn.f32x2 %0, %1, %2, %3;" : "=l"(d) : "l"(a), "l"(b), "l"(c)); return d;
}
__device__ __forceinline__ u64 mul2(u64 a, u64 b) {
    u64 d; asm("mul.rn.f32x2 %0, %1, %2;" : "=l"(d) : "l"(a), "l"(b)); return d;
}
__device__ __forceinline__ u64 pack2(float lo, float hi) {
    u64 d; asm("mov.b64 %0, {%1, %2};" : "=l"(d) : "f"(lo), "f"(hi)); return d;
}
__device__ __forceinline__ u64 splat2(float x) {
    u64 d; asm("mov.b64 %0, {%1, %1};" : "=l"(d) : "f"(x)); return d;
}
__device__ __forceinline__ void unpack2(u64 v, float& lo, float& hi) {
    asm("mov.b64 {%0, %1}, %2;" : "=f"(lo), "=f"(hi) : "l"(v));
}

// ---------------- mma.sync / cp.async helpers ----------------
__device__ __forceinline__ uint32_t smem_u32(const void* p) {
    uint32_t a;
    asm("{ .reg .u64 t; cvta.to.shared.u64 t, %1; cvt.u32.u64 %0, t; }" : "=r"(a) : "l"(p));
    return a;
}
__device__ __forceinline__ void ldsm4(uint32_t* r, uint32_t addr) {
    asm volatile("ldmatrix.sync.aligned.m8n8.x4.shared.b16 {%0,%1,%2,%3}, [%4];"
                 : "=r"(r[0]), "=r"(r[1]), "=r"(r[2]), "=r"(r[3]) : "r"(addr));
}
__device__ __forceinline__ void mma_bf16(float* d, const uint32_t* a, uint32_t b0, uint32_t b1) {
    asm volatile("mma.sync.aligned.m16n8k16.row.col.f32.bf16.bf16.f32 "
                 "{%0,%1,%2,%3},{%4,%5,%6,%7},{%8,%9},{%0,%1,%2,%3};"
                 : "+f"(d[0]), "+f"(d[1]), "+f"(d[2]), "+f"(d[3])
                 : "r"(a[0]), "r"(a[1]), "r"(a[2]), "r"(a[3]), "r"(b0), "r"(b1));
}
__device__ __forceinline__ void cp16(uint32_t saddr, const void* g) {
    asm volatile("cp.async.cg.shared.global [%0], [%1], 16;" :: "r"(saddr), "l"(g));
}
__device__ __forceinline__ uint32_t bf2bits(float a, float b) {
    __nv_bfloat162 p = __floats2bfloat162_rn(a, b);
    return reinterpret_cast<uint32_t&>(p);
}

#define STAGE_B 40960
#define SMEM_DYN (2 * STAGE_B)

// ---------------------------------------------------------------------------
// Prep: convert x and all 4 W matrices to bf16 hi/lo pairs.
// ---------------------------------------------------------------------------
__global__ void __launch_bounds__(256)
prep_kernel(const float4* __restrict__ x,  const float4* __restrict__ wq,
            const float4* __restrict__ wk, const float4* __restrict__ wv,
            const float4* __restrict__ wo)
{
    const int i = blockIdx.x * 256 + threadIdx.x;   // over 1,572,864 float4
    const float4* src; __nv_bfloat16 *dh, *dl; int off;
    if (i < 524288) { src = x; off = i; dh = g_xh; dl = g_xl; }
    else {
        const int r = i - 524288;
        const int w = r >> 18;          // 262144 float4 per weight
        off = r & 262143;
        src = (w == 0) ? wq : (w == 1) ? wk : (w == 2) ? wv : wo;
        dh = g_Wh + (size_t)w * 1048576;
        dl = g_Wl + (size_t)w * 1048576;
    }
    const float4 v = src[off];
    const float hx = __bfloat162float(__float2bfloat16(v.x));
    const float hy = __bfloat162float(__float2bfloat16(v.y));
    const float hz = __bfloat162float(__float2bfloat16(v.z));
    const float hw = __bfloat162float(__float2bfloat16(v.w));
    uint2 Hv = make_uint2(bf2bits(v.x, v.y), bf2bits(v.z, v.w));
    uint2 Lv = make_uint2(bf2bits(v.x - hx, v.y - hy), bf2bits(v.z - hz, v.w - hw));
    *(uint2*)&dh[(size_t)off * 4] = Hv;
    *(uint2*)&dl[(size_t)off * 4] = Lv;
}

// ---------------------------------------------------------------------------
// 3xBF16 HMMA NT GEMM body: dst[m,n] = sum_k A[m,k]*W[n,k], M-tile 128, N-tile
// 128, BK=32, 8 warps (64x32 each). A/B operands pre-split hi/lo bf16.
// ---------------------------------------------------------------------------
template <int REMAP>
__device__ __forceinline__ void store2(float* dst, int m, int n, float v0, float v1) {
    if (REMAP) {
        const int b = m >> 10, c = m & 1023, hd = n >> 4, h = n & 15;
        *(float2*)&dst[(((size_t)(b * 64 + hd)) << 14) + (size_t)c * 16 + h] = make_float2(v0, v1);
    } else {
        *(float2*)&dst[(size_t)m * 1024 + n] = make_float2(v0, v1);
    }
}

template <int REMAP>
__device__ __forceinline__ void gemm_body(
    const __nv_bfloat16* __restrict__ Ah, const __nv_bfloat16* __restrict__ Al,
    const __nv_bfloat16* __restrict__ Bh, const __nv_bfloat16* __restrict__ Bl,
    float* __restrict__ dst, int bm, int bn, uint32_t smb, int t)
{
    const int lane = t & 31, warp = t >> 5;
    const int wm = (warp >> 2) * 64, wn = (warp & 3) * 32;

    float acc[4][4][4] = {};

    // cp.async mapping: 2 chunk ids per thread, 4 tiles each
    const int r0 = t >> 2,        c0 = t & 3;
    const int r1 = (t + 256) >> 2, c1 = (t + 256) & 3;

    // ldmatrix byte offsets within a tile (row stride 80B)
    const uint32_t aoff = (uint32_t)((wm + (lane & 15)) * 80 + (lane >> 4) * 16);
    const uint32_t boff = (uint32_t)((wn + ((lane >> 4) & 1) * 8 + (lane & 7)) * 80 +
                                     ((lane >> 3) & 1) * 16);

    #define PREFETCH(buf, kt) do {                                              \
        const uint32_t sb_ = smb + (buf) * STAGE_B;                              \
        const size_t gA0 = (size_t)(bm + r0) * 1024 + (kt) + c0 * 8;             \
        const size_t gB0 = (size_t)(bn + r0) * 1024 + (kt) + c0 * 8;             \
        const size_t gA1 = (size_t)(bm + r1) * 1024 + (kt) + c1 * 8;             \
        const size_t gB1 = (size_t)(bn + r1) * 1024 + (kt) + c1 * 8;             \
        const uint32_t s0 = sb_ + r0 * 80 + c0 * 16;                             \
        const uint32_t s1 = sb_ + r1 * 80 + c1 * 16;                             \
        cp16(s0,         Ah + gA0);  cp16(s0 + 10240, Al + gA0);                 \
        cp16(s0 + 20480, Bh + gB0);  cp16(s0 + 30720, Bl + gB0);                 \
        cp16(s1,         Ah + gA1);  cp16(s1 + 10240, Al + gA1);                 \
        cp16(s1 + 20480, Bh + gB1);  cp16(s1 + 30720, Bl + gB1);                 \
        asm volatile("cp.async.commit_group;" ::: "memory");                     \
    } while (0)

    PREFETCH(0, 0);
    for (int s = 0; s < 32; s++) {
        if (s + 1 < 32) {
            PREFETCH((s + 1) & 1, (s + 1) * 32);
            asm volatile("cp.async.wait_group 1;" ::: "memory");
        } else {
            asm volatile("cp.async.wait_group 0;" ::: "memory");
        }
        __syncthreads();

        const uint32_t sb = smb + (s & 1) * STAGE_B;
        #pragma unroll
        for (int sp = 0; sp < 3; sp++) {
            const uint32_t at = (sp == 2) ? 10240u : 0u;       // Al : Ah
            const uint32_t bt = (sp == 1) ? 30720u : 20480u;   // Bl : Bh
            #pragma unroll
            for (int ks = 0; ks < 2; ks++) {
                uint32_t a[4][4], b[2][4];
                #pragma unroll
                for (int i = 0; i < 4; i++)
                    ldsm4(a[i], sb + at + aoff + (uint32_t)(i * 16 * 80 + ks * 32));
                #pragma unroll
                for (int jj = 0; jj < 2; jj++)
                    ldsm4(b[jj], sb + bt + boff + (uint32_t)(jj * 16 * 80 + ks * 32));
                #pragma unroll
                for (int i = 0; i < 4; i++)
                    #pragma unroll
                    for (int j = 0; j < 4; j++)
                        mma_bf16(acc[i][j], a[i],
                                 b[j >> 1][(j & 1) * 2], b[j >> 1][(j & 1) * 2 + 1]);
            }
        }
        __syncthreads();
    }
    #undef PREFETCH

    #pragma unroll
    for (int i = 0; i < 4; i++)
        #pragma unroll
        for (int j = 0; j < 4; j++) {
            const int n  = bn + wn + j * 8 + (lane & 3) * 2;
            const int m0 = bm + wm + i * 16 + (lane >> 2);
            store2<REMAP>(dst, m0,     n, acc[i][j][0], acc[i][j][1]);
            store2<REMAP>(dst, m0 + 8, n, acc[i][j][2], acc[i][j][3]);
        }
}

__global__ void __launch_bounds__(256, 1)
gemm_qkv_k()
{
    extern __shared__ char sm[];
    const uint32_t smb = smem_u32(sm);
    const int z = blockIdx.z;
    const __nv_bfloat16* Bh = g_Wh + (size_t)z * 1048576;
    const __nv_bfloat16* Bl = g_Wl + (size_t)z * 1048576;
    float* dst = (z == 0) ? g_Q : (z == 1) ? g_K : g_V;
    gemm_body<1>(g_xh, g_xl, Bh, Bl, dst,
                 blockIdx.y * 128, blockIdx.x * 128, smb, threadIdx.x);
}

__global__ void __launch_bounds__(256, 1)
gemm_o_k(float* __restrict__ out)
{
    extern __shared__ char sm[];
    const uint32_t smb = smem_u32(sm);
    gemm_body<0>(g_AOh, g_AOl, g_Wh + 3u * 1048576, g_Wl + 3u * 1048576, out,
                 blockIdx.y * 128, blockIdx.x * 128, smb, threadIdx.x);
}

// ---------------------------------------------------------------------------
// Flash attention: 2 query rows/thread, LDS.128 K/V; epilogue writes bf16
// hi/lo pairs for the O-projection.
// ---------------------------------------------------------------------------
__global__ void __launch_bounds__(128)
attn_kernel3()
{
    __shared__ __align__(16) float Ks[128][16];
    __shared__ __align__(16) float Vs[128][16];

    const int bh = blockIdx.y;
    const int t  = threadIdx.x;
    const int cq0 = blockIdx.x * 256 + t;
    const int cq1 = cq0 + 128;

    u64 q2[2][8];
    #pragma unroll
    for (int qq = 0; qq < 2; qq++) {
        const float* qp = g_Q + ((size_t)bh * 1024 + (qq ? cq1 : cq0)) * 16;
        #pragma unroll
        for (int i = 0; i < 4; i++) {
            float4 v = *(const float4*)(qp + i * 4);
            q2[qq][i * 2 + 0] = pack2(v.x * 0.25f, v.y * 0.25f);
            q2[qq][i * 2 + 1] = pack2(v.z * 0.25f, v.w * 0.25f);
        }
    }

    float m0 = -1e30f, l0 = 0.0f, m1 = -1e30f, l1 = 0.0f;
    u64 o2[2][8];
    #pragma unroll
    for (int i = 0; i < 8; i++) { o2[0][i] = 0ull; o2[1][i] = 0ull; }

    const float* kbase = g_K + (size_t)bh * 1024 * 16;
    const float* vbase = g_V + (size_t)bh * 1024 * 16;

    for (int kt = 0; kt < 1024; kt += 128) {
        const float4* kp = (const float4*)(kbase + (size_t)(kt + t) * 16);
        const float4* vp = (const float4*)(vbase + (size_t)(kt + t) * 16);
        #pragma unroll
        for (int i = 0; i < 4; i++) {
            ((float4*)Ks[t])[i] = kp[i];
            ((float4*)Vs[t])[i] = vp[i];
        }
        __syncthreads();

        #pragma unroll 1
        for (int c0 = 0; c0 < 128; c0 += 16) {
            float s0[16], s1[16];
            #pragma unroll
            for (int jj = 0; jj < 16; jj++) {
                const ulonglong2* krp = (const ulonglong2*)Ks[c0 + jj];
                ulonglong2 ka = krp[0], kb = krp[1], kc = krp[2], kd = krp[3];
                u64 a0 = mul2(q2[0][0], ka.x);
                u64 a1 = mul2(q2[1][0], ka.x);
                a0 = fma2(q2[0][1], ka.y, a0); a1 = fma2(q2[1][1], ka.y, a1);
                a0 = fma2(q2[0][2], kb.x, a0); a1 = fma2(q2[1][2], kb.x, a1);
                a0 = fma2(q2[0][3], kb.y, a0); a1 = fma2(q2[1][3], kb.y, a1);
                a0 = fma2(q2[0][4], kc.x, a0); a1 = fma2(q2[1][4], kc.x, a1);
                a0 = fma2(q2[0][5], kc.y, a0); a1 = fma2(q2[1][5], kc.y, a1);
                a0 = fma2(q2[0][6], kd.x, a0); a1 = fma2(q2[1][6], kd.x, a1);
                a0 = fma2(q2[0][7], kd.y, a0); a1 = fma2(q2[1][7], kd.y, a1);
                float lo, hi;
                unpack2(a0, lo, hi); s0[jj] = lo + hi;
                unpack2(a1, lo, hi); s1[jj] = lo + hi;
            }
            float cm0 = s0[0], cm1 = s1[0];
            #pragma unroll
            for (int jj = 1; jj < 16; jj++) {
                cm0 = fmaxf(cm0, s0[jj]);
                cm1 = fmaxf(cm1, s1[jj]);
            }
            const float mn0 = fmaxf(m0, cm0);
            const float mn1 = fmaxf(m1, cm1);
            const float cr0 = __expf(m0 - mn0);
            const float cr1 = __expf(m1 - mn1);
            l0 *= cr0; l1 *= cr1;
            const u64 cr02 = splat2(cr0), cr12 = splat2(cr1);
            #pragma unroll
            for (int h = 0; h < 8; h++) {
                o2[0][h] = mul2(o2[0][h], cr02);
                o2[1][h] = mul2(o2[1][h], cr12);
            }

            #pragma unroll
            for (int jj = 0; jj < 16; jj++) {
                const float p0 = __expf(s0[jj] - mn0);
                const float p1 = __expf(s1[jj] - mn1);
                l0 += p0; l1 += p1;
                const u64 pp0 = splat2(p0), pp1 = splat2(p1);
                const ulonglong2* vrp = (const ulonglong2*)Vs[c0 + jj];
                ulonglong2 va = vrp[0], vb = vrp[1], vc = vrp[2], vd = vrp[3];
                o2[0][0] = fma2(pp0, va.x, o2[0][0]); o2[1][0] = fma2(pp1, va.x, o2[1][0]);
                o2[0][1] = fma2(pp0, va.y, o2[0][1]); o2[1][1] = fma2(pp1, va.y, o2[1][1]);
                o2[0][2] = fma2(pp0, vb.x, o2[0][2]); o2[1][2] = fma2(pp1, vb.x, o2[1][2]);
                o2[0][3] = fma2(pp0, vb.y, o2[0][3]); o2[1][3] = fma2(pp1, vb.y, o2[1][3]);
                o2[0][4] = fma2(pp0, vc.x, o2[0][4]); o2[1][4] = fma2(pp1, vc.x, o2[1][4]);
                o2[0][5] = fma2(pp0, vc.y, o2[0][5]); o2[1][5] = fma2(pp1, vc.y, o2[1][5]);
                o2[0][6] = fma2(pp0, vd.x, o2[0][6]); o2[1][6] = fma2(pp1, vd.x, o2[1][6]);
                o2[0][7] = fma2(pp0, vd.y, o2[0][7]); o2[1][7] = fma2(pp1, vd.y, o2[1][7]);
            }
            m0 = mn0; m1 = mn1;
        }
        __syncthreads();
    }

    const int b  = bh >> 6;
    const int hd = bh & 63;
    #pragma unroll
    for (int qq = 0; qq < 2; qq++) {
        const float inv = 1.0f / (qq ? l1 : l0);
        const int c = qq ? cq1 : cq0;
        float v[16];
        #pragma unroll
        for (int i = 0; i < 8; i++) {
            float lo, hi;
            unpack2(o2[qq][i], lo, hi);
            v[i * 2] = lo * inv; v[i * 2 + 1] = hi * inv;
        }
        uint32_t uh[8], ul[8];
        #pragma unroll
        for (int j = 0; j < 8; j++) {
            const float a = v[2 * j], bv = v[2 * j + 1];
            const float ha = __bfloat162float(__float2bfloat16(a));
            const float hb = __bfloat162float(__float2bfloat16(bv));
            uh[j] = bf2bits(a, bv);
            ul[j] = bf2bits(a - ha, bv - hb);
        }
        const size_t ro = ((size_t)(b * 1024 + c)) * 1024 + hd * 16;
        *(uint4*)&g_AOh[ro]     = make_uint4(uh[0], uh[1], uh[2], uh[3]);
        *(uint4*)&g_AOh[ro + 8] = make_uint4(uh[4], uh[5], uh[6], uh[7]);
        *(uint4*)&g_AOl[ro]     = make_uint4(ul[0], ul[1], ul[2], ul[3]);
        *(uint4*)&g_AOl[ro + 8] = make_uint4(ul[4], ul[5], ul[6], ul[7]);
    }
}

// ---------------------------------------------------------------------------
extern "C" void kernel_launch(void* const* d_in, const int* in_sizes, int n_in,
                              void* d_out, int out_size)
{
    const float* x  = (const float*)d_in[0];
    const float* Wq = (const float*)d_in[1];
    const float* Wk = (const float*)d_in[2];
    const float* Wv = (const float*)d_in[3];
    const float* Wo = (const float*)d_in[4];
    float* out = (float*)d_out;

    cudaFuncSetAttribute(gemm_qkv_k, cudaFuncAttributeMaxDynamicSharedMemorySize, SMEM_DYN);
    cudaFuncSetAttribute(gemm_o_k,   cudaFuncAttributeMaxDynamicSharedMemorySize, SMEM_DYN);

    prep_kernel<<<6144, 256>>>((const float4*)x, (const float4*)Wq,
                               (const float4*)Wk, (const float4*)Wv,
                               (const float4*)Wo);

    gemm_qkv_k<<<dim3(8, 16, 3), 256, SMEM_DYN>>>();

    attn_kernel3<<<dim3(1024 / 256, B_ * HD_), 128>>>();

    gemm_o_k<<<dim3(8, 16), 256, SMEM_DYN>>>(out);
}